// round 11
// baseline (speedup 1.0000x reference)
#include <cuda_runtime.h>
#include <cstdint>

#define NROWS 8192
#define DIM 128
#define ALPHA 2.0f
#define SHIFT 40.0f
#define BM 128
#define BN 32
#define JCHUNKS 16
#define TILES 16             // j-tiles per chunk: 512/32
#define NTHREADS 512

__device__ float g_pos_part[JCHUNKS][NROWS];
__device__ float g_neg_part[JCHUNKS][NROWS];
__device__ float g_at_diag[NROWS];
__device__ float g_pt_part[1024];
__device__ double g_fin[64];

// int8 limb arrays: z ~= (h*256 + l) / 4096   (16-bit fixed point, S=8)
__device__ char g_au_h[NROWS * DIM];
__device__ char g_au_l[NROWS * DIM];
__device__ char g_tp_h[NROWS * DIM];
__device__ char g_tp_l[NROWS * DIM];

// smem: A tiles 4 x (128 rows x 144B) = 73728; B double buffer 2 x 4 x (32 x 144B)
#define RSTRIDE 144
#define SA_BYTES 18432       // 128*144
#define SBV_BYTES 4608       // 32*144
#define SB_BASE 73728
#define SB_BUF 18432         // 4 variants
#define SM_TOTAL 110592

__device__ __forceinline__ uint32_t smem_u32(const void* p) {
    uint32_t a;
    asm("{ .reg .u64 t; cvta.to.shared.u64 t, %1; cvt.u32.u64 %0, t; }" : "=r"(a) : "l"(p));
    return a;
}

#define LDSM4(r0, r1, r2, r3, addr)                                              \
    asm volatile("ldmatrix.sync.aligned.m8n8.x4.shared.b16 {%0,%1,%2,%3}, [%4];" \
                 : "=r"(r0), "=r"(r1), "=r"(r2), "=r"(r3) : "r"(addr))

#define MMAI8(d, a, b0r, b1r)                                                   \
    asm volatile("mma.sync.aligned.m16n8k32.row.col.s32.s8.s8.s32 "             \
                 "{%0,%1,%2,%3}, {%4,%5,%6,%7}, {%8,%9}, {%0,%1,%2,%3};"        \
                 : "+r"((d)[0]), "+r"((d)[1]), "+r"((d)[2]), "+r"((d)[3])       \
                 : "r"((a)[0]), "r"((a)[1]), "r"((a)[2]), "r"((a)[3]),          \
                   "r"(b0r), "r"(b1r))

#define CP_ASYNC16(dst, src)                                                    \
    asm volatile("cp.async.cg.shared.global [%0], [%1], 16;"                    \
                 :: "r"(dst), "l"(src) : "memory")
#define CP_COMMIT() asm volatile("cp.async.commit_group;" ::: "memory")
#define CP_WAIT1()  asm volatile("cp.async.wait_group 1;" ::: "memory")
#define CP_WAIT0()  asm volatile("cp.async.wait_group 0;" ::: "memory")

__device__ __forceinline__ int quant_split(float x, int& l) {
    int q = __float2int_rn(x * 4096.0f);
    q = max(-32640, min(32639, q));
    int h = (q + 128) >> 8;
    l = q - (h << 8);
    return h;
}
__device__ __forceinline__ int pack4(int b0, int b1, int b2, int b3) {
    return (b0 & 255) | ((b1 & 255) << 8) | ((b2 & 255) << 16) | ((b3 & 255) << 24);
}

// Fused prep: int8 limb split + exact fp32 diag + pt partials. One read of inputs.
__global__ void prep_kernel(const float* __restrict__ zau, const float* __restrict__ ztp,
                            const float* __restrict__ fc) {
    __shared__ float red[256];
    const int tid = threadIdx.x;
    const int e = blockIdx.x * 256 + tid;          // float4 index
    float4 a = ((const float4*)zau)[e];
    float4 b = ((const float4*)ztp)[e];

    int l0, l1, l2, l3;
    int h0 = quant_split(a.x, l0), h1 = quant_split(a.y, l1);
    int h2 = quant_split(a.z, l2), h3 = quant_split(a.w, l3);
    ((int*)g_au_h)[e] = pack4(h0, h1, h2, h3);
    ((int*)g_au_l)[e] = pack4(l0, l1, l2, l3);
    h0 = quant_split(b.x, l0); h1 = quant_split(b.y, l1);
    h2 = quant_split(b.z, l2); h3 = quant_split(b.w, l3);
    ((int*)g_tp_h)[e] = pack4(h0, h1, h2, h3);
    ((int*)g_tp_l)[e] = pack4(l0, l1, l2, l3);

    // diag: each warp covers exactly one row (32 float4 = 128 floats)
    float s = a.x * b.x + a.y * b.y + a.z * b.z + a.w * b.w;
#pragma unroll
    for (int off = 16; off > 0; off >>= 1)
        s += __shfl_xor_sync(0xffffffff, s, off);
    if ((tid & 31) == 0) g_at_diag[e >> 5] = s;

    // pt partial: (au - tp) . (pt1 - pt0)
    const int c4 = e & 31;
    float4 f0 = ((const float4*)fc)[c4];
    float4 f1 = ((const float4*)fc)[32 + c4];
    float ps = (a.x - b.x) * (f1.x - f0.x) + (a.y - b.y) * (f1.y - f0.y) +
               (a.z - b.z) * (f1.z - f0.z) + (a.w - b.w) * (f1.w - f0.w);
    red[tid] = ps;
    __syncthreads();
    for (int off = 128; off > 0; off >>= 1) {
        if (tid < off) red[tid] += red[tid + off];
        __syncthreads();
    }
    if (tid == 0) g_pt_part[blockIdx.x] = red[0];
}

__global__ __launch_bounds__(NTHREADS, 1)
void supcon_imma(int dummy) {
    extern __shared__ char smem[];
    const uint32_t sb = smem_u32(smem);
    const int tid = threadIdx.x;
    const int wid = tid >> 5, lane = tid & 31;
    const int wm = wid >> 1, wn = wid & 1;          // warp grid 8(M) x 2(N)
    const int m0 = wm * 16, n0 = wn * 16;
    const int g = lane >> 2, t4 = lane & 3;
    const int ibase = blockIdx.x * BM;
    const int jcbase = blockIdx.y * (NROWS / JCHUNKS);

    const char* gsrc[4] = {g_au_h, g_au_l, g_tp_h, g_tp_l};

    // A prologue: 4 variants x 128 rows x 128B, 8 x 16B chunks per thread
#pragma unroll
    for (int a = 0; a < 4; ++a) {
#pragma unroll
        for (int i = 0; i < 2; ++i) {
            int idx = tid + i * NTHREADS;            // 0..1023
            int row = idx >> 3, c = idx & 7;
            CP_ASYNC16(sb + a * SA_BYTES + row * RSTRIDE + c * 16,
                       __cvta_generic_to_global(gsrc[a] + (size_t)(ibase + row) * DIM + c * 16));
        }
    }
    // B tile 0 -> buf0  (grouped with A)
#pragma unroll
    for (int u = 0; u < 2; ++u) {
        int ci = tid + u * NTHREADS;                 // 0..1023
        int v = ci >> 8, rem = ci & 255;
        int row = rem >> 3, c = rem & 7;
        CP_ASYNC16(sb + SB_BASE + v * SBV_BYTES + row * RSTRIDE + c * 16,
                   __cvta_generic_to_global(gsrc[v] + (size_t)(jcbase + row) * DIM + c * 16));
    }
    CP_COMMIT();
    // B tile 1 -> buf1
#pragma unroll
    for (int u = 0; u < 2; ++u) {
        int ci = tid + u * NTHREADS;
        int v = ci >> 8, rem = ci & 255;
        int row = rem >> 3, c = rem & 7;
        CP_ASYNC16(sb + SB_BASE + SB_BUF + v * SBV_BYTES + row * RSTRIDE + c * 16,
                   __cvta_generic_to_global(gsrc[v] + (size_t)(jcbase + 32 + row) * DIM + c * 16));
    }
    CP_COMMIT();

    // ldmatrix lane addressing (16B granules)
    const int rowi = (lane & 7) + ((lane >> 3) & 1) * 8;
    const int kh = ((lane >> 4) & 1) * 16;
    uint32_t aAddr[4];
#pragma unroll
    for (int v = 0; v < 4; ++v)
        aAddr[v] = sb + v * SA_BYTES + (uint32_t)((m0 + rowi) * RSTRIDE + kh);
    const uint32_t boff = (uint32_t)((n0 + rowi) * RSTRIDE + kh);

    const int row_base = ibase + m0 + g;
    float pos_loc[2] = {0.f, 0.f};
    float neg_loc[2] = {0.f, 0.f};

    CP_WAIT1();          // A + B0 complete
    __syncthreads();

    for (int t = 0; t < TILES; ++t) {
        uint32_t bAddr[4];
#pragma unroll
        for (int v = 0; v < 4; ++v)
            bAddr[v] = sb + SB_BASE + (t & 1) * SB_BUF + v * SBV_BYTES + boff;

        int acc[6][2][4];    // [aa_h, aa_m, tt_h, tt_m, at_h, at_m][n][d]
#pragma unroll
        for (int s = 0; s < 6; ++s)
#pragma unroll
            for (int n = 0; n < 2; ++n)
#pragma unroll
                for (int d = 0; d < 4; ++d) acc[s][n][d] = 0;

#pragma unroll
        for (int ks = 0; ks < 4; ++ks) {
            const uint32_t koff = ks * 32;           // 32 int8 of K per step
            uint32_t bF[4][4];
#pragma unroll
            for (int v = 0; v < 4; ++v)
                LDSM4(bF[v][0], bF[v][1], bF[v][2], bF[v][3], bAddr[v] + koff);

            uint32_t aH[4], aL[4];
            LDSM4(aH[0], aH[1], aH[2], aH[3], aAddr[0] + koff);   // au_h
            LDSM4(aL[0], aL[1], aL[2], aL[3], aAddr[1] + koff);   // au_l
#pragma unroll
            for (int n = 0; n < 2; ++n) {
                MMAI8(acc[0][n], aH, bF[0][n], bF[0][n + 2]);   // aa: h*h
                MMAI8(acc[1][n], aH, bF[1][n], bF[1][n + 2]);   // aa: h*l
                MMAI8(acc[1][n], aL, bF[0][n], bF[0][n + 2]);   // aa: l*h
                MMAI8(acc[4][n], aH, bF[2][n], bF[2][n + 2]);   // at: h*h
                MMAI8(acc[5][n], aH, bF[3][n], bF[3][n + 2]);   // at: h*l
                MMAI8(acc[5][n], aL, bF[2][n], bF[2][n + 2]);   // at: l*h
            }
            LDSM4(aH[0], aH[1], aH[2], aH[3], aAddr[2] + koff);   // tp_h
            LDSM4(aL[0], aL[1], aL[2], aL[3], aAddr[3] + koff);   // tp_l
#pragma unroll
            for (int n = 0; n < 2; ++n) {
                MMAI8(acc[2][n], aH, bF[2][n], bF[2][n + 2]);   // tt: h*h
                MMAI8(acc[3][n], aH, bF[3][n], bF[3][n + 2]);   // tt: h*l
                MMAI8(acc[3][n], aL, bF[2][n], bF[2][n + 2]);   // tt: l*h
            }
        }

        __syncthreads();     // everyone done reading buf t&1

        // Prefetch B(t+2) into the buffer just freed; hidden under tile t+1 MMAs.
        if (t + 1 < TILES) {
            if (t + 2 < TILES) {
                const int jn = jcbase + (t + 2) * BN;
#pragma unroll
                for (int u = 0; u < 2; ++u) {
                    int ci = tid + u * NTHREADS;
                    int v = ci >> 8, rem = ci & 255;
                    int row = rem >> 3, c = rem & 7;
                    CP_ASYNC16(sb + SB_BASE + (t & 1) * SB_BUF + v * SBV_BYTES + row * RSTRIDE + c * 16,
                               __cvta_generic_to_global(gsrc[v] + (size_t)(jn + row) * DIM + c * 16));
                }
            }
            CP_COMMIT();     // empty group when t+2 == TILES keeps accounting aligned
        }

        // Epilogue: reconstruct logits, exp-sum with diagonal exclusion.
        const int col_base = jcbase + t * BN + n0 + 2 * t4;
#pragma unroll
        for (int n = 0; n < 2; ++n)
#pragma unroll
            for (int d = 0; d < 4; ++d) {
                const float c16 = 1.0f / 65536.0f;
                float laa = fmaf((float)acc[0][n][d], 256.f, (float)acc[1][n][d]) * c16;
                float ltt = fmaf((float)acc[2][n][d], 256.f, (float)acc[3][n][d]) * c16;
                float lat = fmaf((float)acc[4][n][d], 256.f, (float)acc[5][n][d]) * c16;
                const int gi = row_base + ((d >> 1) << 3);
                const int gj = col_base + n * 8 + (d & 1);
                float e1 = __expf(laa - SHIFT) + __expf(ltt - SHIFT);
                float e2 = __expf(lat - SHIFT);
                if (gi != gj) {
                    pos_loc[d >> 1] += e1;
                    neg_loc[d >> 1] += e2;
                }
            }

        if (t + 1 < TILES) CP_WAIT1();   // B(t+1) guaranteed complete
        __syncthreads();
    }

    // Reduce over t4 lanes, then over the 2 n-warps via smem.
#pragma unroll
    for (int i = 0; i < 2; ++i) {
        pos_loc[i] += __shfl_xor_sync(0xffffffff, pos_loc[i], 1);
        pos_loc[i] += __shfl_xor_sync(0xffffffff, pos_loc[i], 2);
        neg_loc[i] += __shfl_xor_sync(0xffffffff, neg_loc[i], 1);
        neg_loc[i] += __shfl_xor_sync(0xffffffff, neg_loc[i], 2);
    }
    float* rf = (float*)smem;   // [0:256) pos[row][wn], [256:512) neg[row][wn]
    __syncthreads();
    if (t4 == 0) {
#pragma unroll
        for (int i = 0; i < 2; ++i) {
            const int row = m0 + i * 8 + g;
            rf[row * 2 + wn] = pos_loc[i];
            rf[256 + row * 2 + wn] = neg_loc[i];
        }
    }
    __syncthreads();
    if (tid < 128) {
        g_pos_part[blockIdx.y][ibase + tid] = rf[tid * 2] + rf[tid * 2 + 1];
        g_neg_part[blockIdx.y][ibase + tid] = rf[256 + tid * 2] + rf[256 + tid * 2 + 1];
    }
}

// Stage 1: per-row supcon terms (64 blocks x 128 rows)
__global__ void final1_kernel() {
    __shared__ double red[128];
    const int tid = threadIdx.x;
    const int i = blockIdx.x * 128 + tid;
    float ps = 0.f, ns = 0.f;
#pragma unroll
    for (int c = 0; c < JCHUNKS; ++c) {
        ps += g_pos_part[c][i];
        ns += g_neg_part[c][i];
    }
    red[tid] = (double)(logf(ns) - logf(ps) + ALPHA * g_at_diag[i]);
    __syncthreads();
    for (int off = 64; off > 0; off >>= 1) {
        if (tid < off) red[tid] += red[tid + off];
        __syncthreads();
    }
    if (tid == 0) g_fin[blockIdx.x] = red[0];
}

// Stage 2: combine supcon + pt partials
__global__ void final2_kernel(float* __restrict__ out) {
    __shared__ double red[256];
    __shared__ double red2[256];
    const int tid = threadIdx.x;
    double s = 0.0, p = 0.0;
    for (int i = tid; i < 64; i += 256) s += g_fin[i];
    for (int i = tid; i < 1024; i += 256) p += (double)g_pt_part[i];
    red[tid] = s;
    red2[tid] = p;
    __syncthreads();
    for (int off = 128; off > 0; off >>= 1) {
        if (tid < off) { red[tid] += red[tid + off]; red2[tid] += red2[tid + off]; }
        __syncthreads();
    }
    if (tid == 0)
        out[0] = (float)((red2[0] / (double)NROWS + red[0]) / (double)(NROWS + 2));
}

extern "C" void kernel_launch(void* const* d_in, const int* in_sizes, int n_in,
                              void* d_out, int out_size) {
    const float* zau = (const float*)d_in[0];   // [8192,128] f32
    const float* ztp = (const float*)d_in[1];   // [8192,128] f32
    const float* fc  = (const float*)d_in[2];   // [2,128] f32
    // d_in[3]: labels (int64) — unused by the math.
    float* out = (float*)d_out;

    cudaFuncSetAttribute(supcon_imma, cudaFuncAttributeMaxDynamicSharedMemorySize, SM_TOTAL);

    prep_kernel<<<1024, 256>>>(zau, ztp, fc);
    dim3 grid(NROWS / BM, JCHUNKS);
    supcon_imma<<<grid, NTHREADS, SM_TOTAL>>>(0);
    final1_kernel<<<64, 128>>>();
    final2_kernel<<<1, 256>>>(out);
}